// round 16
// baseline (speedup 1.0000x reference)
#include <cuda_runtime.h>
#include <cuda_bf16.h>
#include <cstdint>
#include <cmath>

#define BB   64      // batch
#define TT   1024    // timesteps
#define DD   512     // input dim
#define HH   512     // hidden dim
#define G4   2048    // 4*H
#define NBLK 128     // persistent blocks
#define GBLK 32      // blocks per batch-group barrier

// ---------------- scratch ----------------
__device__ float g_h[2][(size_t)BB * HH];      // double-buffered h
__device__ unsigned int g_barg[4][32];         // per-batch-group counters

__device__ __forceinline__ float sigf(float v) {
    return 1.f / (1.f + __expf(-v));
}

__device__ __forceinline__ float ftanh(float v) {
    const float e = __expf(2.f * v);
    return 1.f - __fdividef(2.f, e + 1.f);
}

__device__ __forceinline__ float to_tf32(float x) {
    float r;
    asm("cvt.rna.tf32.f32 %0, %1;" : "=f"(r) : "f"(x));
    return r;
}

__device__ __forceinline__ void mma_tf32(float* d,
                                         const float* a,
                                         float b0, float b1) {
    asm volatile(
        "mma.sync.aligned.m16n8k8.row.col.f32.tf32.tf32.f32 "
        "{%0,%1,%2,%3},{%4,%5,%6,%7},{%8,%9},{%0,%1,%2,%3};"
        : "+f"(d[0]), "+f"(d[1]), "+f"(d[2]), "+f"(d[3])
        : "r"(__float_as_uint(a[0])), "r"(__float_as_uint(a[1])),
          "r"(__float_as_uint(a[2])), "r"(__float_as_uint(a[3])),
          "r"(__float_as_uint(b0)),  "r"(__float_as_uint(b1)));
}

// =====================================================================
// Fully fused persistent LSTM.
// 128 blocks = 4 batch-groups(16b) x 32 j-groups(16 j x 4 gates).
// Per step: preact[64c][16b] = W.x_t (computed in the previous step's
// barrier-spin shadow, carried in registers) + U.h_{t-1} (TF32 MMA,
// U resident in smem A-frag layout) ; combine k-slices in smem ;
// gate math (+bias) ; h double-buffer ; release/acquire group barrier.
// W A-frags streamed from global (L2-resident), x B-frags use the
// proven h-load lane pattern.
// =====================================================================
#define THR      256
#define UFP      34
#define CMBP     65
#define USF4     (256 * UFP)
#define SMEM_FLOATS (USF4 * 4 + 8 * 16 * CMBP)
#define SMEM_BYTES  (SMEM_FLOATS * 4)  // 172,544 B

__global__ void __launch_bounds__(THR, 1) lstm_fused(
    const float* __restrict__ x,
    const float* __restrict__ Wc, const float* __restrict__ Wi,
    const float* __restrict__ Wf, const float* __restrict__ Wo,
    const float* __restrict__ Uc, const float* __restrict__ Ui,
    const float* __restrict__ Uf, const float* __restrict__ Uo,
    const float* __restrict__ bc, const float* __restrict__ bi,
    const float* __restrict__ bf, const float* __restrict__ bo,
    float* __restrict__ out)
{
    extern __shared__ float sm[];
    float4* Uf4 = reinterpret_cast<float4*>(sm);    // [256 ktig][UFP]
    float*  Cmb = sm + USF4 * 4;                    // [8][16][CMBP]

    const int tid  = threadIdx.x;
    const int bx   = blockIdx.x;
    const int bgrp = bx >> 5;
    const int b0   = bgrp * 16;
    const int jcol0 = (bx & 31) * 16;

    // ---- build A-fragment-layout U in smem (TF32-rounded) ----
    for (int w = tid; w < 8192; w += THR) {
        const int slot = w & 31;
        const int ktig = w >> 5;
        const int mt   = slot >> 3;
        const int gid_ = slot & 7;
        const int tig_ = ktig & 3;
        const int ktg  = ktig >> 2;
        const int k1   = ktg * 8 + tig_;
        const int k2   = k1 + 4;
        const float* Ug = (mt == 0) ? Uc : (mt == 1) ? Ui
                        : (mt == 2) ? Uf : Uo;
        const float* c1 = Ug + jcol0 + gid_;
        float4 v;
        v.x = to_tf32(c1[(size_t)k1 * HH]);
        v.y = to_tf32(c1[(size_t)k1 * HH + 8]);
        v.z = to_tf32(c1[(size_t)k2 * HH]);
        v.w = to_tf32(c1[(size_t)k2 * HH + 8]);
        Uf4[ktig * UFP + slot] = v;
    }

    const int wid  = tid >> 5;        // 0..7 -> k-slice of 64
    const int lane = tid & 31;
    const int gid  = lane >> 2;       // 0..7
    const int tig  = lane & 3;        // 0..3
    const int kw0  = wid * 64;

    const int gjb   = tid >> 4;       // 0..15
    const int gj    = tid & 15;
    const int gb    = b0 + gjb;
    const int jglob = jcol0 + gj;

    // biases for this thread's (jglob) across the 4 gates
    const float bcv = bc[jglob];
    const float biv = bi[jglob];
    const float bfv = bf[jglob];
    const float bov = bo[jglob];

    // h B-frag global offsets (proven pattern)
    const size_t hoff0 = (size_t)(b0 + gid) * HH + kw0 + tig;
    const size_t hoff1 = (size_t)(b0 + 8 + gid) * HH + kw0 + tig;

    // x B-frag base offsets (same lane pattern; x is [B][T][D])
    const size_t xoff0 = ((size_t)(b0 + gid) * TT) * DD + kw0 + tig;
    const size_t xoff1 = ((size_t)(b0 + 8 + gid) * TT) * DD + kw0 + tig;

    // barrier counter (global-space address)
    const unsigned long long barg =
        (unsigned long long)__cvta_generic_to_global(&g_barg[bgrp][0]);

    float cst = 0.f;

    // step-carried accumulators: acc = W.x_t partial (this warp's k-slice)
    float acc[4][2][4];
#pragma unroll
    for (int mt = 0; mt < 4; mt++)
#pragma unroll
        for (int nt = 0; nt < 2; nt++)
#pragma unroll
            for (int r = 0; r < 4; r++) acc[mt][nt][r] = 0.f;

    // ---- prologue: acc = W.x_0 ----
    {
        const float* xb0 = x + xoff0;            // t = 0
        const float* xb1 = x + xoff1;
#pragma unroll
        for (int kt = 0; kt < 8; kt++) {
            float bxf[2][2];
            bxf[0][0] = to_tf32(__ldg(xb0 + kt * 8));
            bxf[0][1] = to_tf32(__ldg(xb0 + kt * 8 + 4));
            bxf[1][0] = to_tf32(__ldg(xb1 + kt * 8));
            bxf[1][1] = to_tf32(__ldg(xb1 + kt * 8 + 4));
            const int krow = kw0 + kt * 8 + tig;
#pragma unroll
            for (int mt = 0; mt < 4; mt++) {
                const float* Wg = (mt == 0) ? Wc : (mt == 1) ? Wi
                                : (mt == 2) ? Wf : Wo;
                const float* r1 = Wg + (size_t)krow * HH + jcol0;
                const float* r2 = r1 + 4 * HH;
                float a[4];
                a[0] = to_tf32(__ldg(r1 + gid));
                a[1] = to_tf32(__ldg(r1 + gid + 8));
                a[2] = to_tf32(__ldg(r2 + gid));
                a[3] = to_tf32(__ldg(r2 + gid + 8));
#pragma unroll
                for (int nt = 0; nt < 2; nt++)
                    mma_tf32(acc[mt][nt], a, bxf[nt][0], bxf[nt][1]);
            }
        }
    }

    __syncthreads();   // U smem ready

    for (int t = 0; t < TT; t++) {
        // ---- U.h accumulation into acc (skip at t==0) ----
        if (t > 0) {
            const float* hb = g_h[t & 1];
            float hv[8][2][2];
#pragma unroll
            for (int kt = 0; kt < 8; kt++) {
                const float* p0 = hb + hoff0 + kt * 8;
                const float* p1 = hb + hoff1 + kt * 8;
                hv[kt][0][0] = __ldcg(p0);
                hv[kt][0][1] = __ldcg(p0 + 4);
                hv[kt][1][0] = __ldcg(p1);
                hv[kt][1][1] = __ldcg(p1 + 4);
            }

#pragma unroll
            for (int kt = 0; kt < 8; kt++) {
                float b1[2][2];
#pragma unroll
                for (int nt = 0; nt < 2; nt++) {
                    b1[nt][0] = to_tf32(hv[kt][nt][0]);
                    b1[nt][1] = to_tf32(hv[kt][nt][1]);
                }
                const float4* ap = Uf4 + ((wid * 8 + kt) * 4 + tig) * UFP + gid;
#pragma unroll
                for (int mt = 0; mt < 4; mt++) {
                    const float4 af = ap[mt * 8];
                    const float a[4] = {af.x, af.y, af.z, af.w};
#pragma unroll
                    for (int nt = 0; nt < 2; nt++)
                        mma_tf32(acc[mt][nt], a, b1[nt][0], b1[nt][1]);
                }
            }
        }

        // ---- write k-slice partials (always: acc holds W.x part) ----
        {
            float* Cq = Cmb + wid * 16 * CMBP;
#pragma unroll
            for (int mt = 0; mt < 4; mt++) {
                const int j0 = mt * 16 + gid;
#pragma unroll
                for (int nt = 0; nt < 2; nt++) {
                    const int bb_ = nt * 8 + 2 * tig;
                    Cq[(bb_ + 0) * CMBP + j0]     = acc[mt][nt][0];
                    Cq[(bb_ + 1) * CMBP + j0]     = acc[mt][nt][1];
                    Cq[(bb_ + 0) * CMBP + j0 + 8] = acc[mt][nt][2];
                    Cq[(bb_ + 1) * CMBP + j0 + 8] = acc[mt][nt][3];
                }
            }
        }
        __syncthreads();

        // ---- sum 8 k-slice partials + bias ----
        float sc = bcv, si = biv, sf = bfv, so = bov;
        {
            const float* Cb = Cmb + gjb * CMBP + gj;
#pragma unroll
            for (int q = 0; q < 8; q++) {
                const float* Cq = Cb + q * 16 * CMBP;
                sc += Cq[0];
                si += Cq[16];
                sf += Cq[32];
                so += Cq[48];
            }
        }

        // ---- gate math ----
        const float a  = ftanh(sc);
        const float ig = sigf(si);
        const float fg = sigf(sf);
        const float og = sigf(so);
        cst = ig * a + fg * cst;
        const float hval = og * ftanh(cst);
        g_h[(t + 1) & 1][(size_t)gb * HH + jglob] = hval;

        // ---- release arrive ----
        __syncthreads();
        if (tid == 0) {
            asm volatile("red.release.gpu.global.add.u32 [%0], %1;"
                         :: "l"(barg), "r"(1u) : "memory");
        }

        // ---- spin-shadow work: out store + W.x_{t+1} into acc ----
        __stcg(out + ((size_t)gb * TT + t) * HH + jglob, hval);

#pragma unroll
        for (int mt = 0; mt < 4; mt++)
#pragma unroll
            for (int nt = 0; nt < 2; nt++)
#pragma unroll
                for (int r = 0; r < 4; r++) acc[mt][nt][r] = 0.f;

        if (t + 1 < TT) {
            const float* xb0 = x + xoff0 + (size_t)(t + 1) * DD;
            const float* xb1 = x + xoff1 + (size_t)(t + 1) * DD;
#pragma unroll
            for (int kt = 0; kt < 8; kt++) {
                float bxf[2][2];
                bxf[0][0] = to_tf32(__ldg(xb0 + kt * 8));
                bxf[0][1] = to_tf32(__ldg(xb0 + kt * 8 + 4));
                bxf[1][0] = to_tf32(__ldg(xb1 + kt * 8));
                bxf[1][1] = to_tf32(__ldg(xb1 + kt * 8 + 4));
                const int krow = kw0 + kt * 8 + tig;
#pragma unroll
                for (int mt = 0; mt < 4; mt++) {
                    const float* Wg = (mt == 0) ? Wc : (mt == 1) ? Wi
                                    : (mt == 2) ? Wf : Wo;
                    const float* r1 = Wg + (size_t)krow * HH + jcol0;
                    const float* r2 = r1 + 4 * HH;
                    float aw[4];
                    aw[0] = to_tf32(__ldg(r1 + gid));
                    aw[1] = to_tf32(__ldg(r1 + gid + 8));
                    aw[2] = to_tf32(__ldg(r2 + gid));
                    aw[3] = to_tf32(__ldg(r2 + gid + 8));
#pragma unroll
                    for (int nt = 0; nt < 2; nt++)
                        mma_tf32(acc[mt][nt], aw, bxf[nt][0], bxf[nt][1]);
                }
            }
        }

        // ---- acquire spin ----
        if (tid == 0) {
            const unsigned tgt = (unsigned)(t + 1) * (unsigned)GBLK;
            unsigned v;
            do {
                asm volatile("ld.acquire.gpu.global.u32 %0, [%1];"
                             : "=r"(v) : "l"(barg) : "memory");
            } while (v < tgt);
        }
        __syncthreads();
    }
}

// =====================================================================
extern "C" void kernel_launch(void* const* d_in, const int* in_sizes, int n_in,
                              void* d_out, int out_size)
{
    const float* x  = (const float*)d_in[0];
    const float* Wc = (const float*)d_in[1];
    const float* Wi = (const float*)d_in[2];
    const float* Wf = (const float*)d_in[3];
    const float* Wo = (const float*)d_in[4];
    const float* Uc = (const float*)d_in[5];
    const float* Ui = (const float*)d_in[6];
    const float* Uf = (const float*)d_in[7];
    const float* Uo = (const float*)d_in[8];
    const float* bc = (const float*)d_in[9];
    const float* bi = (const float*)d_in[10];
    const float* bf = (const float*)d_in[11];
    const float* bo = (const float*)d_in[12];
    float* out = (float*)d_out;

    cudaFuncSetAttribute(lstm_fused,
                         cudaFuncAttributeMaxDynamicSharedMemorySize, SMEM_BYTES);

    void* barp = nullptr;
    cudaGetSymbolAddress(&barp, g_barg);
    cudaMemsetAsync(barp, 0, sizeof(unsigned int) * 4 * 32, 0);

    lstm_fused<<<NBLK, THR, SMEM_BYTES>>>(
        x, Wc, Wi, Wf, Wo, Uc, Ui, Uf, Uo, bc, bi, bf, bo, out);
}

// round 17
// speedup vs baseline: 1.4582x; 1.4582x over previous
#include <cuda_runtime.h>
#include <cuda_bf16.h>
#include <cstdint>
#include <cmath>

#define BB   64      // batch
#define TT   1024    // timesteps
#define DD   512     // input dim
#define HH   512     // hidden dim
#define G4   2048    // 4*H
#define NBLK 128     // persistent blocks
#define GBLK 32      // blocks per batch-group barrier

// ---------------- scratch ----------------
__device__ float g_xp[(size_t)TT * BB * G4];   // [T][B][4H]
__device__ float g_h[2][(size_t)BB * HH];      // double-buffered h
__device__ unsigned int g_barg[4][32];         // per-batch-group counters

__device__ __forceinline__ float sigf(float v) {
    return 1.f / (1.f + __expf(-v));
}

__device__ __forceinline__ float ftanh(float v) {
    const float e = __expf(2.f * v);
    return 1.f - __fdividef(2.f, e + 1.f);
}

__device__ __forceinline__ float to_tf32(float x) {
    float r;
    asm("cvt.rna.tf32.f32 %0, %1;" : "=f"(r) : "f"(x));
    return r;
}

__device__ __forceinline__ void mma_tf32(float* d,
                                         const float* a,
                                         float b0, float b1) {
    asm volatile(
        "mma.sync.aligned.m16n8k8.row.col.f32.tf32.tf32.f32 "
        "{%0,%1,%2,%3},{%4,%5,%6,%7},{%8,%9},{%0,%1,%2,%3};"
        : "+f"(d[0]), "+f"(d[1]), "+f"(d[2]), "+f"(d[3])
        : "r"(__float_as_uint(a[0])), "r"(__float_as_uint(a[1])),
          "r"(__float_as_uint(a[2])), "r"(__float_as_uint(a[3])),
          "r"(__float_as_uint(b0)),  "r"(__float_as_uint(b1)));
}

// =====================================================================
// Phase 1: xproj GEMM on TF32 tensor cores (round-10/13 PROVEN version).
// =====================================================================
#define XPI 136
#define XPROJ_SMEM_BYTES (2 * 32 * XPI * 4)

__global__ void __launch_bounds__(256) xproj_mma(
    const float* __restrict__ x,
    const float* __restrict__ Wc, const float* __restrict__ Wi,
    const float* __restrict__ Wf, const float* __restrict__ Wo,
    const float* __restrict__ bc, const float* __restrict__ bi,
    const float* __restrict__ bf, const float* __restrict__ bo)
{
    extern __shared__ float xsm[];
    float* xs = xsm;
    float* ws = xsm + 32 * XPI;

    const int tid = threadIdx.x;
    const int n0  = blockIdx.x * 128;
    const int m0  = blockIdx.y * 128;
    const int g   = n0 >> 9;
    const int col0 = n0 & 511;

    const float* Wg = (g == 0) ? Wc : (g == 1) ? Wi : (g == 2) ? Wf : Wo;
    const float* bg = (g == 0) ? bc : (g == 1) ? bi : (g == 2) ? bf : bo;

    const int wid  = tid >> 5;
    const int lane = tid & 31;
    const int gid  = lane >> 2;
    const int tig  = lane & 3;
    const int mw0  = (wid & 3) * 32;
    const int nw0  = (wid >> 2) * 64;

    float acc[2][8][4];
#pragma unroll
    for (int mt = 0; mt < 2; mt++)
#pragma unroll
        for (int nt = 0; nt < 8; nt++)
#pragma unroll
            for (int r = 0; r < 4; r++) acc[mt][nt][r] = 0.f;

    for (int k0 = 0; k0 < DD; k0 += 32) {
#pragma unroll
        for (int it = 0; it < 4; it++) {
            const int e   = it * 256 + tid;
            const int row = e >> 3;
            const int kq  = e & 7;
            const float4 v = *reinterpret_cast<const float4*>(
                x + (size_t)(m0 + row) * DD + k0 + kq * 4);
            xs[(kq * 4 + 0) * XPI + row] = to_tf32(v.x);
            xs[(kq * 4 + 1) * XPI + row] = to_tf32(v.y);
            xs[(kq * 4 + 2) * XPI + row] = to_tf32(v.z);
            xs[(kq * 4 + 3) * XPI + row] = to_tf32(v.w);
        }
#pragma unroll
        for (int it = 0; it < 4; it++) {
            const int e  = it * 256 + tid;
            const int kr = e >> 5;
            const int nq = e & 31;
            const float4 v = *reinterpret_cast<const float4*>(
                Wg + (size_t)(k0 + kr) * HH + col0 + nq * 4);
            ws[kr * XPI + nq * 4 + 0] = to_tf32(v.x);
            ws[kr * XPI + nq * 4 + 1] = to_tf32(v.y);
            ws[kr * XPI + nq * 4 + 2] = to_tf32(v.z);
            ws[kr * XPI + nq * 4 + 3] = to_tf32(v.w);
        }
        __syncthreads();

#pragma unroll
        for (int kt = 0; kt < 4; kt++) {
            const int kk = kt * 8;

            float b[8][2];
#pragma unroll
            for (int nt = 0; nt < 8; nt++) {
                const int nn = nw0 + nt * 8 + gid;
                b[nt][0] = ws[(kk + tig) * XPI + nn];
                b[nt][1] = ws[(kk + tig + 4) * XPI + nn];
            }
#pragma unroll
            for (int mt = 0; mt < 2; mt++) {
                const int mm = mw0 + mt * 16 + gid;
                float a[4];
                a[0] = xs[(kk + tig) * XPI + mm];
                a[1] = xs[(kk + tig) * XPI + mm + 8];
                a[2] = xs[(kk + tig + 4) * XPI + mm];
                a[3] = xs[(kk + tig + 4) * XPI + mm + 8];
#pragma unroll
                for (int nt = 0; nt < 8; nt++)
                    mma_tf32(acc[mt][nt], a, b[nt][0], b[nt][1]);
            }
        }
        __syncthreads();
    }

#pragma unroll
    for (int nt = 0; nt < 8; nt++) {
        const int cl = col0 + nw0 + nt * 8 + 2 * tig;
        const float2 bb = *reinterpret_cast<const float2*>(bg + cl);
#pragma unroll
        for (int mt = 0; mt < 2; mt++) {
            const int r0 = m0 + mw0 + mt * 16 + gid;
            const int r1 = r0 + 8;
            const int b0_ = r0 >> 10, t0_ = r0 & 1023;
            const int b1_ = r1 >> 10, t1_ = r1 & 1023;
            float* p0 = g_xp + ((size_t)t0_ * BB + b0_) * G4 + g * HH + cl;
            float* p1 = g_xp + ((size_t)t1_ * BB + b1_) * G4 + g * HH + cl;
            *reinterpret_cast<float2*>(p0) =
                make_float2(acc[mt][nt][0] + bb.x, acc[mt][nt][1] + bb.y);
            *reinterpret_cast<float2*>(p1) =
                make_float2(acc[mt][nt][2] + bb.x, acc[mt][nt][3] + bb.y);
        }
    }
}

// =====================================================================
// Phase 2: persistent recurrence (round-15 structure) with gate-major
// float4 combine: Cmb4[q][b][j] = {gate0,gate1,gate2,gate3}.
// Stores: 8 STS.128/thread; reads: 8 LDS.128/thread. Bit-identical sums.
// =====================================================================
#define THR      256
#define UFP      34
#define CJP      17                     // j pitch (float4) in combine
#define USF4     (256 * UFP)
#define CMBF4    (8 * 16 * CJP)         // 2176 float4
#define SMEM_FLOATS (USF4 * 4 + CMBF4 * 4)
#define SMEM_BYTES  (SMEM_FLOATS * 4)   // 174,080 B

__global__ void __launch_bounds__(THR, 1) lstm_recur(
    const float* __restrict__ Uc, const float* __restrict__ Ui,
    const float* __restrict__ Uf, const float* __restrict__ Uo,
    float* __restrict__ out)
{
    extern __shared__ float sm[];
    float4* Uf4  = reinterpret_cast<float4*>(sm);          // [256 ktig][UFP]
    float4* Cmb4 = reinterpret_cast<float4*>(sm + USF4 * 4); // [8][16][CJP]

    const int tid  = threadIdx.x;
    const int bx   = blockIdx.x;
    const int bgrp = bx >> 5;
    const int b0   = bgrp * 16;
    const int jcol0 = (bx & 31) * 16;

    // ---- build A-fragment-layout U in smem (TF32-rounded) ----
    for (int w = tid; w < 8192; w += THR) {
        const int slot = w & 31;
        const int ktig = w >> 5;
        const int mt   = slot >> 3;
        const int gid_ = slot & 7;
        const int tig_ = ktig & 3;
        const int ktg  = ktig >> 2;
        const int k1   = ktg * 8 + tig_;
        const int k2   = k1 + 4;
        const float* Ug = (mt == 0) ? Uc : (mt == 1) ? Ui
                        : (mt == 2) ? Uf : Uo;
        const float* c1 = Ug + jcol0 + gid_;
        float4 v;
        v.x = to_tf32(c1[(size_t)k1 * HH]);
        v.y = to_tf32(c1[(size_t)k1 * HH + 8]);
        v.z = to_tf32(c1[(size_t)k2 * HH]);
        v.w = to_tf32(c1[(size_t)k2 * HH + 8]);
        Uf4[ktig * UFP + slot] = v;
    }

    const int wid  = tid >> 5;
    const int lane = tid & 31;
    const int gid  = lane >> 2;
    const int tig  = lane & 3;
    const int kw0  = wid * 64;

    const int gjb   = tid >> 4;
    const int gj    = tid & 15;
    const int gb    = b0 + gjb;
    const int jglob = jcol0 + gj;

    const size_t hoff0 = (size_t)(b0 + gid) * HH + kw0 + tig;
    const size_t hoff1 = (size_t)(b0 + 8 + gid) * HH + kw0 + tig;

    const unsigned long long barg =
        (unsigned long long)__cvta_generic_to_global(&g_barg[bgrp][0]);

    float cst = 0.f;

    const float* xp0 = g_xp + (size_t)gb * G4 + jglob;
    float xc = __ldcs(xp0);
    float xi = __ldcs(xp0 + HH);
    float xf = __ldcs(xp0 + 2 * HH);
    float xo = __ldcs(xp0 + 3 * HH);

    __syncthreads();

    for (int t = 0; t < TT; t++) {
        float sc = 0.f, si = 0.f, sf = 0.f, so = 0.f;

        if (t > 0) {
            const float* hb = g_h[t & 1];
            float hv[8][2][2];
#pragma unroll
            for (int kt = 0; kt < 8; kt++) {
                const float* p0 = hb + hoff0 + kt * 8;
                const float* p1 = hb + hoff1 + kt * 8;
                hv[kt][0][0] = __ldcg(p0);
                hv[kt][0][1] = __ldcg(p0 + 4);
                hv[kt][1][0] = __ldcg(p1);
                hv[kt][1][1] = __ldcg(p1 + 4);
            }

            float da[4][2][4];
#pragma unroll
            for (int mt = 0; mt < 4; mt++)
#pragma unroll
                for (int nt = 0; nt < 2; nt++)
#pragma unroll
                    for (int r = 0; r < 4; r++) da[mt][nt][r] = 0.f;

#pragma unroll
            for (int kt = 0; kt < 8; kt++) {
                float b1[2][2];
#pragma unroll
                for (int nt = 0; nt < 2; nt++) {
                    b1[nt][0] = to_tf32(hv[kt][nt][0]);
                    b1[nt][1] = to_tf32(hv[kt][nt][1]);
                }

                const float4* ap = Uf4 + ((wid * 8 + kt) * 4 + tig) * UFP + gid;
#pragma unroll
                for (int mt = 0; mt < 4; mt++) {
                    const float4 af = ap[mt * 8];
                    const float a[4] = {af.x, af.y, af.z, af.w};
#pragma unroll
                    for (int nt = 0; nt < 2; nt++)
                        mma_tf32(da[mt][nt], a, b1[nt][0], b1[nt][1]);
                }
            }

            // ---- write k-slice partials, gate-major float4 ----
            // D element (mt,nt,r) lives at b = nt*8+2*tig+(r&1),
            // j = gid+8*(r>>1); pack the 4 gates (mt) into one float4.
            {
                float4* Cq = Cmb4 + wid * 16 * CJP;
#pragma unroll
                for (int nt = 0; nt < 2; nt++)
#pragma unroll
                    for (int r = 0; r < 4; r++) {
                        const int b_ = nt * 8 + 2 * tig + (r & 1);
                        const int j_ = gid + 8 * (r >> 1);
                        Cq[b_ * CJP + j_] =
                            make_float4(da[0][nt][r], da[1][nt][r],
                                        da[2][nt][r], da[3][nt][r]);
                    }
            }
            __syncthreads();

            // ---- sum 8 k-slice partials (float4 = 4 gates) ----
            const float4* Cb = Cmb4 + gjb * CJP + gj;
#pragma unroll
            for (int q = 0; q < 8; q++) {
                const float4 v = Cb[q * 16 * CJP];
                sc += v.x;
                si += v.y;
                sf += v.z;
                so += v.w;
            }
        }

        const float a  = ftanh(xc + sc);
        const float ig = sigf(xi + si);
        const float fg = sigf(xf + sf);
        const float og = sigf(xo + so);
        cst = ig * a + fg * cst;
        const float hval = og * ftanh(cst);
        g_h[(t + 1) & 1][(size_t)gb * HH + jglob] = hval;

        // ---- release arrive ----
        __syncthreads();
        if (tid == 0) {
            asm volatile("red.release.gpu.global.add.u32 [%0], %1;"
                         :: "l"(barg), "r"(1u) : "memory");
        }

        // ---- off-critical-path work while siblings arrive ----
        __stcg(out + ((size_t)gb * TT + t) * HH + jglob, hval);
        if (t + 1 < TT) {
            const float* xp = g_xp + ((size_t)(t + 1) * BB + gb) * G4 + jglob;
            xc = __ldcs(xp);
            xi = __ldcs(xp + HH);
            xf = __ldcs(xp + 2 * HH);
            xo = __ldcs(xp + 3 * HH);
        }

        // ---- acquire spin ----
        if (tid == 0) {
            const unsigned tgt = (unsigned)(t + 1) * (unsigned)GBLK;
            unsigned v;
            do {
                asm volatile("ld.acquire.gpu.global.u32 %0, [%1];"
                             : "=r"(v) : "l"(barg) : "memory");
            } while (v < tgt);
        }
        __syncthreads();
    }
}

// =====================================================================
extern "C" void kernel_launch(void* const* d_in, const int* in_sizes, int n_in,
                              void* d_out, int out_size)
{
    const float* x  = (const float*)d_in[0];
    const float* Wc = (const float*)d_in[1];
    const float* Wi = (const float*)d_in[2];
    const float* Wf = (const float*)d_in[3];
    const float* Wo = (const float*)d_in[4];
    const float* Uc = (const float*)d_in[5];
    const float* Ui = (const float*)d_in[6];
    const float* Uf = (const float*)d_in[7];
    const float* Uo = (const float*)d_in[8];
    const float* bc = (const float*)d_in[9];
    const float* bi = (const float*)d_in[10];
    const float* bf = (const float*)d_in[11];
    const float* bo = (const float*)d_in[12];
    float* out = (float*)d_out;

    cudaFuncSetAttribute(lstm_recur,
                         cudaFuncAttributeMaxDynamicSharedMemorySize, SMEM_BYTES);
    cudaFuncSetAttribute(xproj_mma,
                         cudaFuncAttributeMaxDynamicSharedMemorySize, XPROJ_SMEM_BYTES);

    void* barp = nullptr;
    cudaGetSymbolAddress(&barp, g_barg);
    cudaMemsetAsync(barp, 0, sizeof(unsigned int) * 4 * 32, 0);

    dim3 g1(G4 / 128, (BB * TT) / 128);   // 16 x 512
    xproj_mma<<<g1, 256, XPROJ_SMEM_BYTES>>>(x, Wc, Wi, Wf, Wo, bc, bi, bf, bo);

    lstm_recur<<<NBLK, THR, SMEM_BYTES>>>(Uc, Ui, Uf, Uo, out);
}